// round 13
// baseline (speedup 1.0000x reference)
#include <cuda_runtime.h>
#include <cuda_bf16.h>
#include <cstdint>

#define N_NODES 50000
#define N_EDGES 800000
#define IN_NODE 128
#define HID 64
#define INV_SQRT8 0.35355339059327373f

typedef unsigned long long ull;

// ---------------- scratch (device globals; no allocation allowed) ----------
__device__ float g_Q[N_NODES * HID];
__device__ float g_K[N_NODES * HID];
__device__ float g_V[N_NODES * HID];
__device__ float g_z[N_NODES * 8];
__device__ float g_cnt[N_NODES];
__device__ int   g_is64;

// ---------------- helpers ---------------------------------------------------
static __device__ __forceinline__ void fma2(ull& d, ull a, ull b) {
    asm("fma.rn.f32x2 %0,%1,%2,%3;" : "=l"(d) : "l"(a), "l"(b), "l"(d));
}
static __device__ __forceinline__ float2 up2(ull v) {
    float2 f;
    asm("mov.b64 {%0,%1},%2;" : "=f"(f.x), "=f"(f.y) : "l"(v));
    return f;
}
static __device__ __forceinline__ void red_add_v2(float* p, float x, float y) {
    asm volatile("red.global.add.v2.f32 [%0],{%1,%2};" ::"l"(p), "f"(x), "f"(y)
                 : "memory");
}
static __device__ __forceinline__ void red_add_f32(float* p, float x) {
    asm volatile("red.global.add.f32 [%0],%1;" ::"l"(p), "f"(x) : "memory");
}
static __device__ __forceinline__ long long get_idx(const void* ei, long long i,
                                                    int is64) {
    if (is64) return ((const long long*)ei)[i];
    return (long long)((const int*)ei)[i];
}
// HMMA: D(16x8,f32) += A(16x16,bf16,row) * B(16x8,bf16,col) — baseline PTX, sm_80+
static __device__ __forceinline__ void mma_bf16(float* d, uint32_t a0,
                                                uint32_t a1, uint32_t a2,
                                                uint32_t a3, uint32_t b0,
                                                uint32_t b1) {
    asm("mma.sync.aligned.m16n8k16.row.col.f32.bf16.bf16.f32 "
        "{%0,%1,%2,%3},{%4,%5,%6,%7},{%8,%9},{%0,%1,%2,%3};"
        : "+f"(d[0]), "+f"(d[1]), "+f"(d[2]), "+f"(d[3])
        : "r"(a0), "r"(a1), "r"(a2), "r"(a3), "r"(b0), "r"(b1));
}

// ------------- dummy + zero/detect -----------------------------------------
__global__ void dummy_kernel() {}

__global__ void zero_detect_kernel(const void* ei) {
    int i = blockIdx.x * blockDim.x + threadIdx.x;
    if (i == 0) {
        const long long* p = (const long long*)ei;
        int ok = 1;
        for (int t = 0; t < 16; t++) {
            long long v = p[t];
            if (v < 0 || v >= N_NODES) ok = 0;
        }
        g_is64 = ok;
    }
    float4 z4 = make_float4(0.f, 0.f, 0.f, 0.f);
    if (i < N_NODES * 2) ((float4*)g_z)[i] = z4;
    if (i < N_NODES / 4) ((float4*)g_cnt)[i] = z4;
}

// ------------- fused node projections (benchmarked R3 version) --------------
__global__ void __launch_bounds__(512)
proj_fused_kernel(const float* __restrict__ h, const float* __restrict__ WQ,
                  const float* __restrict__ bQ, const float* __restrict__ WK,
                  const float* __restrict__ bK, const float* __restrict__ WV,
                  const float* __restrict__ bV) {
    extern __shared__ float sm[];
    float* Wq = sm;
    float* Wk = sm + 8192;
    float* Wv = sm + 16384;
    float* hsd = sm + 24576;

    int tid = threadIdx.x;
    #pragma unroll
    for (int i = tid; i < 2048; i += 512) {
        ((float4*)Wq)[i] = ((const float4*)WQ)[i];
        ((float4*)Wk)[i] = ((const float4*)WK)[i];
        ((float4*)Wv)[i] = ((const float4*)WV)[i];
    }
    __syncthreads();

    int warp = tid >> 5, lane = tid & 31;
    long long nbase = ((long long)blockIdx.x * 16 + warp) * 4;
    if (nbase >= N_NODES) return;

    float* hw = hsd + warp * 1024;
    {
        const float4* s4 = (const float4*)(h + nbase * IN_NODE);
        #pragma unroll
        for (int u = 0; u < 4; u++) {
            int i = lane + u * 32;
            float4 v = s4[i];
            float* dst = hw + (i >> 5) * 256 + ((i & 31) << 3);
            *(float4*)(dst) = make_float4(v.x, v.x, v.y, v.y);
            *(float4*)(dst + 4) = make_float4(v.z, v.z, v.w, v.w);
        }
    }
    __syncwarp();

    int co = 2 * lane;
    ull aq[4], ak[4], av[4];
    {
        ull bq = *(const ull*)&bQ[co];
        ull bk = *(const ull*)&bK[co];
        ull bv = *(const ull*)&bV[co];
        #pragma unroll
        for (int j = 0; j < 4; j++) { aq[j] = bq; ak[j] = bk; av[j] = bv; }
    }

    #pragma unroll 4
    for (int k = 0; k < IN_NODE; k++) {
        ull wq = *(const ull*)&Wq[k * HID + co];
        ull wk = *(const ull*)&Wk[k * HID + co];
        ull wv = *(const ull*)&Wv[k * HID + co];
        #pragma unroll
        for (int j = 0; j < 4; j++) {
            ull ev = *(const ull*)&hw[j * 256 + 2 * k];
            fma2(aq[j], ev, wq);
            fma2(ak[j], ev, wk);
            fma2(av[j], ev, wv);
        }
    }

    #pragma unroll
    for (int j = 0; j < 4; j++) {
        long long o = (nbase + j) * HID + co;
        *(float2*)&g_Q[o] = up2(aq[j]);
        *(float2*)&g_K[o] = up2(ak[j]);
        *(float2*)&g_V[o] = up2(av[j]);
    }
}

// ------------- edge kernel: mma.sync bf16-split GEMM + fused epilogue -------
// Tile = 128 edges; warp w owns rows 32w..32w+31 end-to-end (stage, GEMM,
// epilogue) -> warp-independent, only __syncwarp. B = We^T staged once.
// Smem rows: 64 bf16 = 128B, 16B-chunk XOR swizzle (chunk ^ (row&7)) ->
// conflict-free fragment LDS, structural-min STS.
#define EOFF_AHI 0
#define EOFF_ALO 16384
#define EOFF_BHI 32768
#define EOFF_BLO 40960
#define EOFF_SI  49152
#define EOFF_DI  49664
#define EOFF_BE  50176
#define EDGE_SMEM 50432

static __device__ __forceinline__ int sw_off(int row, int chunk, int t) {
    return row * 128 + (((chunk) ^ (row & 7)) << 4) + 4 * t;
}

__global__ void __launch_bounds__(128, 4)
edge_mma_kernel(const void* __restrict__ ei, const float* __restrict__ e,
                const float* __restrict__ We, const float* __restrict__ be,
                float* __restrict__ e_out) {
    extern __shared__ char smc[];
    int tid = threadIdx.x, w = tid >> 5, lane = tid & 31;
    int g = lane >> 2, t = lane & 3;
    int is64 = g_is64;

    // one-time: stage B = We^T (bf16 hi/lo, swizzled) + be
    for (int i = tid; i < 4096; i += 128) {
        int k = i >> 6, n = i & 63;   // read We[k][n] coalesced
        float v = We[i];
        __nv_bfloat16 hi = __float2bfloat16(v);
        __nv_bfloat16 lo = __float2bfloat16(v - __bfloat162float(hi));
        int off = n * 128 + (((k >> 3) ^ (n & 7)) << 4) + (k & 7) * 2;
        *(__nv_bfloat16*)(smc + EOFF_BHI + off) = hi;
        *(__nv_bfloat16*)(smc + EOFF_BLO + off) = lo;
    }
    if (tid < 64) ((float*)(smc + EOFF_BE))[tid] = be[tid];
    __syncthreads();

    int* si = (int*)(smc + EOFF_SI);
    int* di = (int*)(smc + EOFF_DI);
    const float* bes = (const float*)(smc + EOFF_BE);

    for (long long tt = blockIdx.x; tt < N_EDGES / 128; tt += gridDim.x) {
        long long base = tt * 128;

        // ---- stage: this thread owns edge row `tid` ----
        {
            long long E = base + tid;
            si[tid] = (int)get_idx(ei, E, is64);
            di[tid] = (int)get_idx(ei, (long long)N_EDGES + E, is64);
            const float4* src = (const float4*)(e + E * HID);
            #pragma unroll
            for (int c = 0; c < 8; c++) {
                float4 f0 = src[2 * c], f1 = src[2 * c + 1];
                __nv_bfloat162 h0 = __floats2bfloat162_rn(f0.x, f0.y);
                __nv_bfloat162 h1 = __floats2bfloat162_rn(f0.z, f0.w);
                __nv_bfloat162 h2 = __floats2bfloat162_rn(f1.x, f1.y);
                __nv_bfloat162 h3 = __floats2bfloat162_rn(f1.z, f1.w);
                __nv_bfloat162 l0 = __floats2bfloat162_rn(
                    f0.x - __bfloat162float(h0.x), f0.y - __bfloat162float(h0.y));
                __nv_bfloat162 l1 = __floats2bfloat162_rn(
                    f0.z - __bfloat162float(h1.x), f0.w - __bfloat162float(h1.y));
                __nv_bfloat162 l2 = __floats2bfloat162_rn(
                    f1.x - __bfloat162float(h2.x), f1.y - __bfloat162float(h2.y));
                __nv_bfloat162 l3 = __floats2bfloat162_rn(
                    f1.z - __bfloat162float(h3.x), f1.w - __bfloat162float(h3.y));
                int off = tid * 128 + ((c ^ (tid & 7)) << 4);
                *(uint4*)(smc + EOFF_AHI + off) =
                    make_uint4(*(uint32_t*)&h0, *(uint32_t*)&h1,
                               *(uint32_t*)&h2, *(uint32_t*)&h3);
                *(uint4*)(smc + EOFF_ALO + off) =
                    make_uint4(*(uint32_t*)&l0, *(uint32_t*)&l1,
                               *(uint32_t*)&l2, *(uint32_t*)&l3);
            }
        }
        __syncwarp();

        // ---- GEMM: warp computes rows 32w..32w+31, all 64 cols ----
        float d[2][8][4];
        #pragma unroll
        for (int ms = 0; ms < 2; ms++)
            #pragma unroll
            for (int nc = 0; nc < 8; nc++)
                #pragma unroll
                for (int j = 0; j < 4; j++) d[ms][nc][j] = 0.0f;

        #pragma unroll
        for (int ks = 0; ks < 4; ks++) {
            uint32_t ah[2][4], al[2][4];
            #pragma unroll
            for (int ms = 0; ms < 2; ms++) {
                int r0 = 32 * w + 16 * ms + g, r1 = r0 + 8;
                ah[ms][0] = *(uint32_t*)(smc + EOFF_AHI + sw_off(r0, 2 * ks, t));
                ah[ms][1] = *(uint32_t*)(smc + EOFF_AHI + sw_off(r1, 2 * ks, t));
                ah[ms][2] = *(uint32_t*)(smc + EOFF_AHI + sw_off(r0, 2 * ks + 1, t));
                ah[ms][3] = *(uint32_t*)(smc + EOFF_AHI + sw_off(r1, 2 * ks + 1, t));
                al[ms][0] = *(uint32_t*)(smc + EOFF_ALO + sw_off(r0, 2 * ks, t));
                al[ms][1] = *(uint32_t*)(smc + EOFF_ALO + sw_off(r1, 2 * ks, t));
                al[ms][2] = *(uint32_t*)(smc + EOFF_ALO + sw_off(r0, 2 * ks + 1, t));
                al[ms][3] = *(uint32_t*)(smc + EOFF_ALO + sw_off(r1, 2 * ks + 1, t));
            }
            #pragma unroll
            for (int nc = 0; nc < 8; nc++) {
                int n0 = 8 * nc + g;
                uint32_t bh0 = *(uint32_t*)(smc + EOFF_BHI + sw_off(n0, 2 * ks, t));
                uint32_t bh1 = *(uint32_t*)(smc + EOFF_BHI + sw_off(n0, 2 * ks + 1, t));
                uint32_t bl0 = *(uint32_t*)(smc + EOFF_BLO + sw_off(n0, 2 * ks, t));
                uint32_t bl1 = *(uint32_t*)(smc + EOFF_BLO + sw_off(n0, 2 * ks + 1, t));
                #pragma unroll
                for (int ms = 0; ms < 2; ms++) {
                    mma_bf16(d[ms][nc], ah[ms][0], ah[ms][1], ah[ms][2],
                             ah[ms][3], bh0, bh1);
                    mma_bf16(d[ms][nc], ah[ms][0], ah[ms][1], ah[ms][2],
                             ah[ms][3], bl0, bl1);
                    mma_bf16(d[ms][nc], al[ms][0], al[ms][1], al[ms][2],
                             al[ms][3], bh0, bh1);
                }
            }
        }
        __syncwarp();  // A-smem reads done before next tile's stores

        // ---- epilogue (in-fragment) ----
        #pragma unroll
        for (int ms = 0; ms < 2; ms++) {
            #pragma unroll
            for (int hh = 0; hh < 2; hh++) {
                int r = 32 * w + 16 * ms + 8 * hh + g;
                long long E = base + r;
                long long s = si[r], dd = di[r];
                const float2* Kp = (const float2*)&g_K[s * HID];
                const float2* Qp = (const float2*)&g_Q[dd * HID];
                float2* eo = (float2*)&e_out[E * HID];
                float hs[8];
                #pragma unroll
                for (int nc = 0; nc < 8; nc++) {
                    int p2 = 4 * nc + t;             // float2 index = (8nc+2t)/2
                    float2 kv = Kp[p2], qv = Qp[p2];
                    float2 bev = *(const float2*)&bes[8 * nc + 2 * t];
                    float sc0 = fmaf(kv.x * qv.x, INV_SQRT8,
                                     d[ms][nc][2 * hh] + bev.x);
                    float sc1 = fmaf(kv.y * qv.y, INV_SQRT8,
                                     d[ms][nc][2 * hh + 1] + bev.y);
                    eo[p2] = make_float2(sc0, sc1);
                    hs[nc] = sc0 + sc1;
                }
                #pragma unroll
                for (int nc = 0; nc < 8; nc++) {
                    hs[nc] += __shfl_xor_sync(0xffffffffu, hs[nc], 1);
                    hs[nc] += __shfl_xor_sync(0xffffffffu, hs[nc], 2);
                }
                float a0 = __expf(fminf(fmaxf(hs[2 * t], -5.0f), 5.0f));
                float a1 = __expf(fminf(fmaxf(hs[2 * t + 1], -5.0f), 5.0f));
                red_add_v2(&g_z[s * 8 + 2 * t], a0, a1);
                if (t == 0) red_add_f32(&g_cnt[s], 1.0f);
            }
        }
        __syncwarp();
    }
}

// ------------- final: h_out[n,h,:] = V[n,h,:]*S_h/(S_h/max(cnt,1)+1e-6) ----
__global__ void final_kernel(float* __restrict__ h_out) {
    int i = blockIdx.x * blockDim.x + threadIdx.x;
    if (i >= N_NODES * HID / 4) return;
    int n = i >> 4;
    int cg = i & 15;
    float S = g_z[n * 8 + (cg >> 1)];
    float cnt = g_cnt[n];
    float f = S / (S / fmaxf(cnt, 1.0f) + 1e-6f);
    float4 v = ((const float4*)g_V)[i];
    v.x *= f; v.y *= f; v.z *= f; v.w *= f;
    ((float4*)h_out)[i] = v;
}

// ---------------------------------------------------------------------------
extern "C" void kernel_launch(void* const* d_in, const int* in_sizes, int n_in,
                              void* d_out, int out_size) {
    const void* ei = d_in[0];
    const float* h = (const float*)d_in[1];
    const float* e = (const float*)d_in[2];
    const float* WQ = (const float*)d_in[3];
    const float* bQ = (const float*)d_in[4];
    const float* WK = (const float*)d_in[5];
    const float* bK = (const float*)d_in[6];
    const float* WV = (const float*)d_in[7];
    const float* bV = (const float*)d_in[8];
    const float* We = (const float*)d_in[9];
    const float* be = (const float*)d_in[10];

    float* out = (float*)d_out;
    float* h_out = out;
    float* e_out = out + (long long)N_NODES * HID;

    static int attr_done = 0;
    const int PROJ_SMEM = (24576 + 16 * 1024) * 4;  // 163840 B
    if (!attr_done) {
        cudaFuncSetAttribute(proj_fused_kernel,
                             cudaFuncAttributeMaxDynamicSharedMemorySize,
                             PROJ_SMEM);
        cudaFuncSetAttribute(edge_mma_kernel,
                             cudaFuncAttributeMaxDynamicSharedMemorySize,
                             EDGE_SMEM);
        attr_done = 1;
    }

    dummy_kernel<<<1, 32>>>();   // keeps ncu's captured launch on the edge kernel
    zero_detect_kernel<<<391, 256>>>(ei);
    proj_fused_kernel<<<782, 512, PROJ_SMEM>>>(h, WQ, bQ, WK, bK, WV, bV);
    edge_mma_kernel<<<592, 128, EDGE_SMEM>>>(ei, e, We, be, e_out);
    final_kernel<<<(N_NODES * HID / 4 + 255) / 256, 256>>>(h_out);
}

// round 15
// speedup vs baseline: 1.2861x; 1.2861x over previous
#include <cuda_runtime.h>
#include <cuda_bf16.h>
#include <cstdint>

#define N_NODES 50000
#define N_EDGES 800000
#define IN_NODE 128
#define HID 64
#define INV_SQRT8 0.35355339059327373f

typedef unsigned long long ull;

// ---------------- scratch (device globals; no allocation allowed) ----------
__device__ float g_Q[N_NODES * HID];
__device__ float g_K[N_NODES * HID];
__device__ float g_V[N_NODES * HID];
__device__ float g_z[N_NODES * 8];
__device__ float g_cnt[N_NODES];
__device__ int   g_is64;

// ---------------- helpers ---------------------------------------------------
static __device__ __forceinline__ void fma2(ull& d, ull a, ull b) {
    asm("fma.rn.f32x2 %0,%1,%2,%3;" : "=l"(d) : "l"(a), "l"(b), "l"(d));
}
static __device__ __forceinline__ float2 up2(ull v) {
    float2 f;
    asm("mov.b64 {%0,%1},%2;" : "=f"(f.x), "=f"(f.y) : "l"(v));
    return f;
}
static __device__ __forceinline__ ull dup2(float x) {
    ull r;
    asm("mov.b64 %0,{%1,%1};" : "=l"(r) : "f"(x));
    return r;
}
static __device__ __forceinline__ void red_add_v2(float* p, float x, float y) {
    asm volatile("red.global.add.v2.f32 [%0],{%1,%2};" ::"l"(p), "f"(x), "f"(y)
                 : "memory");
}
static __device__ __forceinline__ void red_add_f32(float* p, float x) {
    asm volatile("red.global.add.f32 [%0],%1;" ::"l"(p), "f"(x) : "memory");
}
static __device__ __forceinline__ long long get_idx(const void* ei, long long i,
                                                    int is64) {
    if (is64) return ((const long long*)ei)[i];
    return (long long)((const int*)ei)[i];
}
// HMMA: D(16x8,f32) += A(16x16,bf16,row) * B(16x8,bf16,col) — baseline PTX
static __device__ __forceinline__ void mma_bf16(float* d, uint32_t a0,
                                                uint32_t a1, uint32_t a2,
                                                uint32_t a3, uint32_t b0,
                                                uint32_t b1) {
    asm("mma.sync.aligned.m16n8k16.row.col.f32.bf16.bf16.f32 "
        "{%0,%1,%2,%3},{%4,%5,%6,%7},{%8,%9},{%0,%1,%2,%3};"
        : "+f"(d[0]), "+f"(d[1]), "+f"(d[2]), "+f"(d[3])
        : "r"(a0), "r"(a1), "r"(a2), "r"(a3), "r"(b0), "r"(b1));
}

// ------------- dummy + zero/detect -----------------------------------------
__global__ void dummy_kernel() {}

__global__ void zero_detect_kernel(const void* ei) {
    int i = blockIdx.x * blockDim.x + threadIdx.x;
    if (i == 0) {
        const long long* p = (const long long*)ei;
        int ok = 1;
        for (int t = 0; t < 16; t++) {
            long long v = p[t];
            if (v < 0 || v >= N_NODES) ok = 0;
        }
        g_is64 = ok;
    }
    float4 z4 = make_float4(0.f, 0.f, 0.f, 0.f);
    if (i < N_NODES * 2) ((float4*)g_z)[i] = z4;
    if (i < N_NODES / 4) ((float4*)g_cnt)[i] = z4;
}

// ------------- fused node projections (benchmarked R8 node-pair version) ----
__global__ void __launch_bounds__(512)
proj_fused_kernel(const float* __restrict__ h, const float* __restrict__ WQ,
                  const float* __restrict__ bQ, const float* __restrict__ WK,
                  const float* __restrict__ bK, const float* __restrict__ WV,
                  const float* __restrict__ bV) {
    extern __shared__ float sm[];
    float* Wq = sm;               // 8192 floats
    float* Wk = sm + 8192;        // 8192
    float* Wv = sm + 16384;       // 8192
    float* hts = sm + 24576;      // 16 warps * 512 floats (128k x 4 nodes)

    int tid = threadIdx.x;
    #pragma unroll
    for (int i = tid; i < 2048; i += 512) {
        ((float4*)Wq)[i] = ((const float4*)WQ)[i];
        ((float4*)Wk)[i] = ((const float4*)WK)[i];
        ((float4*)Wv)[i] = ((const float4*)WV)[i];
    }
    __syncthreads();

    int warp = tid >> 5, lane = tid & 31;
    long long nbase = ((long long)blockIdx.x * 16 + warp) * 4;
    if (nbase >= N_NODES) return;

    float* ht = hts + warp * 512;
    {
        const float4* s4 = (const float4*)(h + nbase * IN_NODE);
        #pragma unroll
        for (int u = 0; u < 4; u++) {
            int i = lane + u * 32;
            float4 v = s4[i];
            int row = i >> 5, k0 = (i & 31) << 2;
            ht[(k0 + 0) * 4 + row] = v.x;
            ht[(k0 + 1) * 4 + row] = v.y;
            ht[(k0 + 2) * 4 + row] = v.z;
            ht[(k0 + 3) * 4 + row] = v.w;
        }
    }
    __syncwarp();

    int co = 2 * lane;
    ull aq[2][2], ak[2][2], av[2][2];
    {
        float2 q2 = *(const float2*)&bQ[co];
        float2 k2 = *(const float2*)&bK[co];
        float2 v2 = *(const float2*)&bV[co];
        aq[0][0] = aq[1][0] = dup2(q2.x); aq[0][1] = aq[1][1] = dup2(q2.y);
        ak[0][0] = ak[1][0] = dup2(k2.x); ak[0][1] = ak[1][1] = dup2(k2.y);
        av[0][0] = av[1][0] = dup2(v2.x); av[0][1] = av[1][1] = dup2(v2.y);
    }

    #pragma unroll 4
    for (int k = 0; k < IN_NODE; k++) {
        ulonglong2 ev = *(const ulonglong2*)&ht[k * 4];
        float2 wq = *(const float2*)&Wq[k * HID + co];
        float2 wk = *(const float2*)&Wk[k * HID + co];
        float2 wv = *(const float2*)&Wv[k * HID + co];
        ull wqa = dup2(wq.x), wqb = dup2(wq.y);
        ull wka = dup2(wk.x), wkb = dup2(wk.y);
        ull wva = dup2(wv.x), wvb = dup2(wv.y);
        fma2(aq[0][0], ev.x, wqa); fma2(aq[0][1], ev.x, wqb);
        fma2(aq[1][0], ev.y, wqa); fma2(aq[1][1], ev.y, wqb);
        fma2(ak[0][0], ev.x, wka); fma2(ak[0][1], ev.x, wkb);
        fma2(ak[1][0], ev.y, wka); fma2(ak[1][1], ev.y, wkb);
        fma2(av[0][0], ev.x, wva); fma2(av[0][1], ev.x, wvb);
        fma2(av[1][0], ev.y, wva); fma2(av[1][1], ev.y, wvb);
    }

    #pragma unroll
    for (int p = 0; p < 2; p++) {
        float2 qc0 = up2(aq[p][0]), qc1 = up2(aq[p][1]);
        float2 kc0 = up2(ak[p][0]), kc1 = up2(ak[p][1]);
        float2 vc0 = up2(av[p][0]), vc1 = up2(av[p][1]);
        long long o0 = (nbase + 2 * p) * HID + co;
        long long o1 = (nbase + 2 * p + 1) * HID + co;
        *(float2*)&g_Q[o0] = make_float2(qc0.x, qc1.x);
        *(float2*)&g_Q[o1] = make_float2(qc0.y, qc1.y);
        *(float2*)&g_K[o0] = make_float2(kc0.x, kc1.x);
        *(float2*)&g_K[o1] = make_float2(kc0.y, kc1.y);
        *(float2*)&g_V[o0] = make_float2(vc0.x, vc1.x);
        *(float2*)&g_V[o1] = make_float2(vc0.y, vc1.y);
    }
}

// ------------- edge kernel v2: coalesced staging + 2-round K/Q epilogue -----
#define EOFF_AHI 0
#define EOFF_ALO 16384
#define EOFF_BHI 32768
#define EOFF_BLO 40960
#define EOFF_SI  49152
#define EOFF_DI  49664
#define EOFF_BE  50176
#define EDGE_SMEM 50432

static __device__ __forceinline__ int sw_off(int row, int chunk, int t) {
    return row * 128 + (((chunk) ^ (row & 7)) << 4) + 4 * t;
}
// K/Q staging: fp32 rows 256B, 8B-chunk XOR swizzle (chunk ^ 4*(row&7))
static __device__ __forceinline__ int kq_off(int rl, int c2) {
    return rl * 256 + (((c2) ^ ((rl & 7) << 2)) << 3);
}

__global__ void __launch_bounds__(128, 4)
edge_mma_kernel(const void* __restrict__ ei, const float* __restrict__ e,
                const float* __restrict__ We, const float* __restrict__ be,
                float* __restrict__ e_out) {
    extern __shared__ char smc[];
    int tid = threadIdx.x, w = tid >> 5, lane = tid & 31;
    int g = lane >> 2, t = lane & 3;
    int is64 = g_is64;

    // one-time: stage B = We^T (bf16 hi/lo, swizzled) + be
    for (int i = tid; i < 4096; i += 128) {
        int k = i >> 6, n = i & 63;
        float v = We[i];
        __nv_bfloat16 hi = __float2bfloat16(v);
        __nv_bfloat16 lo = __float2bfloat16(v - __bfloat162float(hi));
        int off = n * 128 + (((k >> 3) ^ (n & 7)) << 4) + (k & 7) * 2;
        *(__nv_bfloat16*)(smc + EOFF_BHI + off) = hi;
        *(__nv_bfloat16*)(smc + EOFF_BLO + off) = lo;
    }
    if (tid < 64) ((float*)(smc + EOFF_BE))[tid] = be[tid];
    __syncthreads();

    int* si = (int*)(smc + EOFF_SI);
    int* di = (int*)(smc + EOFF_DI);
    const float* bes = (const float*)(smc + EOFF_BE);
    char* Ksm = smc + EOFF_AHI + w * 4096;  // reused after GEMM (4 KB)
    char* Qsm = smc + EOFF_ALO + w * 4096;  // reused after GEMM (4 KB)

    for (long long tt = blockIdx.x; tt < N_EDGES / 128; tt += gridDim.x) {
        long long base = tt * 128;

        // ---- indices: thread per row ----
        {
            long long E = base + tid;
            si[tid] = (int)get_idx(ei, E, is64);
            di[tid] = (int)get_idx(ei, (long long)N_EDGES + E, is64);
        }

        // ---- coalesced A stage: warp's 32 rows, 16 contiguous LDG.128 ----
        {
            const float4* src = (const float4*)(e + (base + 32 * w) * HID);
            #pragma unroll
            for (int u = 0; u < 16; u++) {
                int j = u * 32 + lane;        // 512 float4 per warp block
                float4 f = src[j];
                int rl = j >> 4, c = j & 15;  // row-local, fp32 16B chunk
                __nv_bfloat162 h0 = __floats2bfloat162_rn(f.x, f.y);
                __nv_bfloat162 h1 = __floats2bfloat162_rn(f.z, f.w);
                __nv_bfloat162 l0 = __floats2bfloat162_rn(
                    f.x - __bfloat162float(h0.x), f.y - __bfloat162float(h0.y));
                __nv_bfloat162 l1 = __floats2bfloat162_rn(
                    f.z - __bfloat162float(h1.x), f.w - __bfloat162float(h1.y));
                int row = 32 * w + rl;
                int off = row * 128 + (((c >> 1) ^ (row & 7)) << 4) +
                          (c & 1) * 8;
                *(uint2*)(smc + EOFF_AHI + off) =
                    make_uint2(*(uint32_t*)&h0, *(uint32_t*)&h1);
                *(uint2*)(smc + EOFF_ALO + off) =
                    make_uint2(*(uint32_t*)&l0, *(uint32_t*)&l1);
            }
        }
        __syncwarp();

        // ---- GEMM: warp computes its 32 rows x 64 cols ----
        float d[2][8][4];
        #pragma unroll
        for (int ms = 0; ms < 2; ms++)
            #pragma unroll
            for (int nc = 0; nc < 8; nc++)
                #pragma unroll
                for (int j = 0; j < 4; j++) d[ms][nc][j] = 0.0f;

        #pragma unroll
        for (int ks = 0; ks < 4; ks++) {
            uint32_t ah[2][4], al[2][4];
            #pragma unroll
            for (int ms = 0; ms < 2; ms++) {
                int r0 = 32 * w + 16 * ms + g, r1 = r0 + 8;
                ah[ms][0] = *(uint32_t*)(smc + EOFF_AHI + sw_off(r0, 2 * ks, t));
                ah[ms][1] = *(uint32_t*)(smc + EOFF_AHI + sw_off(r1, 2 * ks, t));
                ah[ms][2] = *(uint32_t*)(smc + EOFF_AHI + sw_off(r0, 2 * ks + 1, t));
                ah[ms][3] = *(uint32_t*)(smc + EOFF_AHI + sw_off(r1, 2 * ks + 1, t));
                al[ms][0] = *(uint32_t*)(smc + EOFF_ALO + sw_off(r0, 2 * ks, t));
                al[ms][1] = *(uint32_t*)(smc + EOFF_ALO + sw_off(r1, 2 * ks, t));
                al[ms][2] = *(uint32_t*)(smc + EOFF_ALO + sw_off(r0, 2 * ks + 1, t));
                al[ms][3] = *(uint32_t*)(smc + EOFF_ALO + sw_off(r1, 2 * ks + 1, t));
            }
            #pragma unroll
            for (int nc = 0; nc < 8; nc++) {
                int n0 = 8 * nc + g;
                uint32_t bh0 = *(uint32_t*)(smc + EOFF_BHI + sw_off(n0, 2 * ks, t));
                uint32_t bh1 = *(uint32_t*)(smc + EOFF_BHI + sw_off(n0, 2 * ks + 1, t));
                uint32_t bl0 = *(uint32_t*)(smc + EOFF_BLO + sw_off(n0, 2 * ks, t));
                uint32_t bl1 = *(uint32_t*)(smc + EOFF_BLO + sw_off(n0, 2 * ks + 1, t));
                #pragma unroll
                for (int ms = 0; ms < 2; ms++) {
                    mma_bf16(d[ms][nc], ah[ms][0], ah[ms][1], ah[ms][2],
                             ah[ms][3], bh0, bh1);
                    mma_bf16(d[ms][nc], ah[ms][0], ah[ms][1], ah[ms][2],
                             ah[ms][3], bl0, bl1);
                    mma_bf16(d[ms][nc], al[ms][0], al[ms][1], al[ms][2],
                             al[ms][3], bh0, bh1);
                }
            }
        }
        __syncwarp();  // A reads done; A smem now reusable as K/Q buffers

        // ---- epilogue: two 16-row rounds with coalesced K/Q smem gather ----
        #pragma unroll
        for (int ms = 0; ms < 2; ms++) {
            {   // gather K[s], Q[d] rows: 2 rows per LDG.128 request
                int rowpair = lane >> 4, c = lane & 15;
                #pragma unroll
                for (int pp = 0; pp < 8; pp++) {
                    int rl = 2 * pp + rowpair;
                    int rb = 32 * w + 16 * ms + rl;
                    long long s = si[rb], dd = di[rb];
                    float4 kv = *(const float4*)&g_K[s * HID + c * 4];
                    float4 qv = *(const float4*)&g_Q[dd * HID + c * 4];
                    int off = kq_off(rl, 2 * c);
                    *(float4*)(Ksm + off) = kv;
                    *(float4*)(Qsm + off) = qv;
                }
            }
            __syncwarp();

            #pragma unroll
            for (int hh = 0; hh < 2; hh++) {
                int rl = g + 8 * hh;
                int rb = 32 * w + 16 * ms + rl;
                long long E = base + rb;
                long long s = si[rb];
                float2* eo = (float2*)&e_out[E * HID];
                float hs[8];
                #pragma unroll
                for (int nc = 0; nc < 8; nc++) {
                    float2 kv = *(const float2*)(Ksm + kq_off(rl, 4 * nc + t));
                    float2 qv = *(const float2*)(Qsm + kq_off(rl, 4 * nc + t));
                    float2 bev = *(const float2*)&bes[8 * nc + 2 * t];
                    float sc0 = fmaf(kv.x * qv.x, INV_SQRT8,
                                     d[ms][nc][2 * hh] + bev.x);
                    float sc1 = fmaf(kv.y * qv.y, INV_SQRT8,
                                     d[ms][nc][2 * hh + 1] + bev.y);
                    eo[4 * nc + t] = make_float2(sc0, sc1);
                    hs[nc] = sc0 + sc1;
                }
                #pragma unroll
                for (int nc = 0; nc < 8; nc++) {
                    hs[nc] += __shfl_xor_sync(0xffffffffu, hs[nc], 1);
                    hs[nc] += __shfl_xor_sync(0xffffffffu, hs[nc], 2);
                }
                float a0 = __expf(fminf(fmaxf(hs[2 * t], -5.0f), 5.0f));
                float a1 = __expf(fminf(fmaxf(hs[2 * t + 1], -5.0f), 5.0f));
                red_add_v2(&g_z[s * 8 + 2 * t], a0, a1);
                if (t == 0) red_add_f32(&g_cnt[s], 1.0f);
            }
            __syncwarp();
        }
    }
}

// ------------- final: h_out[n,h,:] = V[n,h,:]*S_h/(S_h/max(cnt,1)+1e-6) ----
__global__ void final_kernel(float* __restrict__ h_out) {
    int i = blockIdx.x * blockDim.x + threadIdx.x;
    if (i >= N_NODES * HID / 4) return;
    int n = i >> 4;
    int cg = i & 15;
    float S = g_z[n * 8 + (cg >> 1)];
    float cnt = g_cnt[n];
    float f = S / (S / fmaxf(cnt, 1.0f) + 1e-6f);
    float4 v = ((const float4*)g_V)[i];
    v.x *= f; v.y *= f; v.z *= f; v.w *= f;
    ((float4*)h_out)[i] = v;
}

// ---------------------------------------------------------------------------
extern "C" void kernel_launch(void* const* d_in, const int* in_sizes, int n_in,
                              void* d_out, int out_size) {
    const void* ei = d_in[0];
    const float* h = (const float*)d_in[1];
    const float* e = (const float*)d_in[2];
    const float* WQ = (const float*)d_in[3];
    const float* bQ = (const float*)d_in[4];
    const float* WK = (const float*)d_in[5];
    const float* bK = (const float*)d_in[6];
    const float* WV = (const float*)d_in[7];
    const float* bV = (const float*)d_in[8];
    const float* We = (const float*)d_in[9];
    const float* be = (const float*)d_in[10];

    float* out = (float*)d_out;
    float* h_out = out;
    float* e_out = out + (long long)N_NODES * HID;

    static int attr_done = 0;
    const int PROJ_SMEM = (24576 + 16 * 512) * 4;  // 131072 B
    if (!attr_done) {
        cudaFuncSetAttribute(proj_fused_kernel,
                             cudaFuncAttributeMaxDynamicSharedMemorySize,
                             PROJ_SMEM);
        cudaFuncSetAttribute(edge_mma_kernel,
                             cudaFuncAttributeMaxDynamicSharedMemorySize,
                             EDGE_SMEM);
        attr_done = 1;
    }

    dummy_kernel<<<1, 32>>>();   // keeps ncu's captured launch on the edge kernel
    zero_detect_kernel<<<391, 256>>>(ei);
    proj_fused_kernel<<<782, 512, PROJ_SMEM>>>(h, WQ, bQ, WK, bK, WV, bV);
    edge_mma_kernel<<<592, 128, EDGE_SMEM>>>(ei, e, We, be, e_out);
    final_kernel<<<(N_NODES * HID / 4 + 255) / 256, 256>>>(h_out);
}

// round 17
// speedup vs baseline: 1.3797x; 1.0727x over previous
#include <cuda_runtime.h>
#include <cuda_bf16.h>
#include <cstdint>

#define N_NODES 50000
#define N_EDGES 800000
#define IN_NODE 128
#define HID 64
#define INV_SQRT8 0.35355339059327373f

typedef unsigned long long ull;

// ---------------- scratch (device globals; no allocation allowed) ----------
__device__ float g_Q[N_NODES * HID];
__device__ float g_K[N_NODES * HID];
__device__ float g_V[N_NODES * HID];
__device__ float g_z[N_NODES * 8];
__device__ float g_cnt[N_NODES];
__device__ int   g_is64;

// ---------------- helpers ---------------------------------------------------
static __device__ __forceinline__ void fma2(ull& d, ull a, ull b) {
    asm("fma.rn.f32x2 %0,%1,%2,%3;" : "=l"(d) : "l"(a), "l"(b), "l"(d));
}
static __device__ __forceinline__ float2 up2(ull v) {
    float2 f;
    asm("mov.b64 {%0,%1},%2;" : "=f"(f.x), "=f"(f.y) : "l"(v));
    return f;
}
static __device__ __forceinline__ ull dup2(float x) {
    ull r;
    asm("mov.b64 %0,{%1,%1};" : "=l"(r) : "f"(x));
    return r;
}
static __device__ __forceinline__ void red_add_v2(float* p, float x, float y) {
    asm volatile("red.global.add.v2.f32 [%0],{%1,%2};" ::"l"(p), "f"(x), "f"(y)
                 : "memory");
}
static __device__ __forceinline__ void red_add_f32(float* p, float x) {
    asm volatile("red.global.add.f32 [%0],%1;" ::"l"(p), "f"(x) : "memory");
}
static __device__ __forceinline__ long long get_idx(const void* ei, long long i,
                                                    int is64) {
    if (is64) return ((const long long*)ei)[i];
    return (long long)((const int*)ei)[i];
}
static __device__ __forceinline__ uint32_t smem_u32(const void* p) {
    uint32_t a;
    asm("{ .reg .u64 t; cvta.to.shared.u64 t, %1; cvt.u32.u64 %0, t; }"
        : "=r"(a) : "l"(p));
    return a;
}
// HMMA: D(16x8,f32) += A(16x16,bf16,row) * B(16x8,bf16,col) — baseline PTX
static __device__ __forceinline__ void mma_bf16(float* d, uint32_t a0,
                                                uint32_t a1, uint32_t a2,
                                                uint32_t a3, uint32_t b0,
                                                uint32_t b1) {
    asm("mma.sync.aligned.m16n8k16.row.col.f32.bf16.bf16.f32 "
        "{%0,%1,%2,%3},{%4,%5,%6,%7},{%8,%9},{%0,%1,%2,%3};"
        : "+f"(d[0]), "+f"(d[1]), "+f"(d[2]), "+f"(d[3])
        : "r"(a0), "r"(a1), "r"(a2), "r"(a3), "r"(b0), "r"(b1));
}
#define LDSM4(r0, r1, r2, r3, addr) \
    asm volatile("ldmatrix.sync.aligned.m8n8.x4.shared.b16 {%0,%1,%2,%3}, [%4];" \
                 : "=r"(r0), "=r"(r1), "=r"(r2), "=r"(r3) : "r"(addr))

// ------------- dummy + zero/detect -----------------------------------------
__global__ void dummy_kernel() {}

__global__ void zero_detect_kernel(const void* ei) {
    int i = blockIdx.x * blockDim.x + threadIdx.x;
    if (i == 0) {
        const long long* p = (const long long*)ei;
        int ok = 1;
        for (int t = 0; t < 16; t++) {
            long long v = p[t];
            if (v < 0 || v >= N_NODES) ok = 0;
        }
        g_is64 = ok;
    }
    float4 z4 = make_float4(0.f, 0.f, 0.f, 0.f);
    if (i < N_NODES * 2) ((float4*)g_z)[i] = z4;
    if (i < N_NODES / 4) ((float4*)g_cnt)[i] = z4;
}

// ------------- fused node projections (benchmarked R8 node-pair version) ----
__global__ void __launch_bounds__(512)
proj_fused_kernel(const float* __restrict__ h, const float* __restrict__ WQ,
                  const float* __restrict__ bQ, const float* __restrict__ WK,
                  const float* __restrict__ bK, const float* __restrict__ WV,
                  const float* __restrict__ bV) {
    extern __shared__ float sm[];
    float* Wq = sm;               // 8192 floats
    float* Wk = sm + 8192;        // 8192
    float* Wv = sm + 16384;       // 8192
    float* hts = sm + 24576;      // 16 warps * 512 floats (128k x 4 nodes)

    int tid = threadIdx.x;
    #pragma unroll
    for (int i = tid; i < 2048; i += 512) {
        ((float4*)Wq)[i] = ((const float4*)WQ)[i];
        ((float4*)Wk)[i] = ((const float4*)WK)[i];
        ((float4*)Wv)[i] = ((const float4*)WV)[i];
    }
    __syncthreads();

    int warp = tid >> 5, lane = tid & 31;
    long long nbase = ((long long)blockIdx.x * 16 + warp) * 4;
    if (nbase >= N_NODES) return;

    float* ht = hts + warp * 512;
    {
        const float4* s4 = (const float4*)(h + nbase * IN_NODE);
        #pragma unroll
        for (int u = 0; u < 4; u++) {
            int i = lane + u * 32;
            float4 v = s4[i];
            int row = i >> 5, k0 = (i & 31) << 2;
            ht[(k0 + 0) * 4 + row] = v.x;
            ht[(k0 + 1) * 4 + row] = v.y;
            ht[(k0 + 2) * 4 + row] = v.z;
            ht[(k0 + 3) * 4 + row] = v.w;
        }
    }
    __syncwarp();

    int co = 2 * lane;
    ull aq[2][2], ak[2][2], av[2][2];
    {
        float2 q2 = *(const float2*)&bQ[co];
        float2 k2 = *(const float2*)&bK[co];
        float2 v2 = *(const float2*)&bV[co];
        aq[0][0] = aq[1][0] = dup2(q2.x); aq[0][1] = aq[1][1] = dup2(q2.y);
        ak[0][0] = ak[1][0] = dup2(k2.x); ak[0][1] = ak[1][1] = dup2(k2.y);
        av[0][0] = av[1][0] = dup2(v2.x); av[0][1] = av[1][1] = dup2(v2.y);
    }

    #pragma unroll 4
    for (int k = 0; k < IN_NODE; k++) {
        ulonglong2 ev = *(const ulonglong2*)&ht[k * 4];
        float2 wq = *(const float2*)&Wq[k * HID + co];
        float2 wk = *(const float2*)&Wk[k * HID + co];
        float2 wv = *(const float2*)&Wv[k * HID + co];
        ull wqa = dup2(wq.x), wqb = dup2(wq.y);
        ull wka = dup2(wk.x), wkb = dup2(wk.y);
        ull wva = dup2(wv.x), wvb = dup2(wv.y);
        fma2(aq[0][0], ev.x, wqa); fma2(aq[0][1], ev.x, wqb);
        fma2(aq[1][0], ev.y, wqa); fma2(aq[1][1], ev.y, wqb);
        fma2(ak[0][0], ev.x, wka); fma2(ak[0][1], ev.x, wkb);
        fma2(ak[1][0], ev.y, wka); fma2(ak[1][1], ev.y, wkb);
        fma2(av[0][0], ev.x, wva); fma2(av[0][1], ev.x, wvb);
        fma2(av[1][0], ev.y, wva); fma2(av[1][1], ev.y, wvb);
    }

    #pragma unroll
    for (int p = 0; p < 2; p++) {
        float2 qc0 = up2(aq[p][0]), qc1 = up2(aq[p][1]);
        float2 kc0 = up2(ak[p][0]), kc1 = up2(ak[p][1]);
        float2 vc0 = up2(av[p][0]), vc1 = up2(av[p][1]);
        long long o0 = (nbase + 2 * p) * HID + co;
        long long o1 = (nbase + 2 * p + 1) * HID + co;
        *(float2*)&g_Q[o0] = make_float2(qc0.x, qc1.x);
        *(float2*)&g_Q[o1] = make_float2(qc0.y, qc1.y);
        *(float2*)&g_K[o0] = make_float2(kc0.x, kc1.x);
        *(float2*)&g_K[o1] = make_float2(kc0.y, kc1.y);
        *(float2*)&g_V[o0] = make_float2(vc0.x, vc1.x);
        *(float2*)&g_V[o1] = make_float2(vc0.y, vc1.y);
    }
}

// ------------- edge kernel v3: ldmatrix fragment loads ----------------------
#define EOFF_AHI 0
#define EOFF_ALO 16384
#define EOFF_BHI 32768
#define EOFF_BLO 40960
#define EOFF_SI  49152
#define EOFF_DI  49664
#define EOFF_BE  50176
#define EDGE_SMEM 50432

// K/Q staging: fp32 rows 256B, 8B-chunk XOR swizzle (chunk ^ 4*(row&7))
static __device__ __forceinline__ int kq_off(int rl, int c2) {
    return rl * 256 + (((c2) ^ ((rl & 7) << 2)) << 3);
}

__global__ void __launch_bounds__(128, 4)
edge_mma_kernel(const void* __restrict__ ei, const float* __restrict__ e,
                const float* __restrict__ We, const float* __restrict__ be,
                float* __restrict__ e_out) {
    extern __shared__ char smc[];
    uint32_t sb = smem_u32(smc);
    int tid = threadIdx.x, w = tid >> 5, lane = tid & 31;
    int g = lane >> 2, t = lane & 3;
    int is64 = g_is64;

    // one-time: stage B = We^T (bf16 hi/lo, swizzled) + be
    for (int i = tid; i < 4096; i += 128) {
        int k = i >> 6, n = i & 63;
        float v = We[i];
        __nv_bfloat16 hi = __float2bfloat16(v);
        __nv_bfloat16 lo = __float2bfloat16(v - __bfloat162float(hi));
        int off = n * 128 + (((k >> 3) ^ (n & 7)) << 4) + (k & 7) * 2;
        *(__nv_bfloat16*)(smc + EOFF_BHI + off) = hi;
        *(__nv_bfloat16*)(smc + EOFF_BLO + off) = lo;
    }
    if (tid < 64) ((float*)(smc + EOFF_BE))[tid] = be[tid];
    __syncthreads();

    int* si = (int*)(smc + EOFF_SI);
    int* di = (int*)(smc + EOFF_DI);
    const float* bes = (const float*)(smc + EOFF_BE);
    char* Ksm = smc + EOFF_AHI + w * 4096;  // reused after GEMM (4 KB)
    char* Qsm = smc + EOFF_ALO + w * 4096;  // reused after GEMM (4 KB)

    // ldmatrix per-thread constant address components
    int lx = lane & 7;                      // swizzle XOR key (row&7 == lane&7)
    int rA = 32 * w + ((lane >> 3) & 1) * 8 + lx;   // A row (ms adds 16)
    int cA = lane >> 4;                              // A chunk offset 0/1
    int nB = ((lane >> 4) & 1) * 8 + lx;             // B n-row (16j adds)
    int cB = (lane >> 3) & 1;                        // B chunk offset 0/1

    for (long long tt = blockIdx.x; tt < N_EDGES / 128; tt += gridDim.x) {
        long long base = tt * 128;

        // ---- indices: thread per row ----
        {
            long long E = base + tid;
            si[tid] = (int)get_idx(ei, E, is64);
            di[tid] = (int)get_idx(ei, (long long)N_EDGES + E, is64);
        }

        // ---- coalesced A stage: warp's 32 rows, 16 contiguous LDG.128 ----
        {
            const float4* src = (const float4*)(e + (base + 32 * w) * HID);
            #pragma unroll
            for (int u = 0; u < 16; u++) {
                int j = u * 32 + lane;        // 512 float4 per warp block
                float4 f = src[j];
                int rl = j >> 4, c = j & 15;  // row-local, fp32 16B chunk
                __nv_bfloat162 h0 = __floats2bfloat162_rn(f.x, f.y);
                __nv_bfloat162 h1 = __floats2bfloat162_rn(f.z, f.w);
                __nv_bfloat162 l0 = __floats2bfloat162_rn(
                    f.x - __bfloat162float(h0.x), f.y - __bfloat162float(h0.y));
                __nv_bfloat162 l1 = __floats2bfloat162_rn(
                    f.z - __bfloat162float(h1.x), f.w - __bfloat162float(h1.y));
                int row = 32 * w + rl;
                int off = row * 128 + (((c >> 1) ^ (row & 7)) << 4) +
                          (c & 1) * 8;
                *(uint2*)(smc + EOFF_AHI + off) =
                    make_uint2(*(uint32_t*)&h0, *(uint32_t*)&h1);
                *(uint2*)(smc + EOFF_ALO + off) =
                    make_uint2(*(uint32_t*)&l0, *(uint32_t*)&l1);
            }
        }
        __syncwarp();

        // ---- GEMM via ldmatrix: warp computes its 32 rows x 64 cols ----
        float d[2][8][4];
        #pragma unroll
        for (int ms = 0; ms < 2; ms++)
            #pragma unroll
            for (int nc = 0; nc < 8; nc++)
                #pragma unroll
                for (int j = 0; j < 4; j++) d[ms][nc][j] = 0.0f;

        #pragma unroll
        for (int ks = 0; ks < 4; ks++) {
            uint32_t ah[2][4], al[2][4];
            #pragma unroll
            for (int ms = 0; ms < 2; ms++) {
                uint32_t off = (uint32_t)((rA + 16 * ms) * 128 +
                                          (((2 * ks + cA) ^ lx) << 4));
                LDSM4(ah[ms][0], ah[ms][1], ah[ms][2], ah[ms][3],
                      sb + EOFF_AHI + off);
                LDSM4(al[ms][0], al[ms][1], al[ms][2], al[ms][3],
                      sb + EOFF_ALO + off);
            }
            #pragma unroll
            for (int jj = 0; jj < 4; jj++) {
                uint32_t off = (uint32_t)((16 * jj + nB) * 128 +
                                          (((2 * ks + cB) ^ lx) << 4));
                uint32_t bh[4], bl[4];
                LDSM4(bh[0], bh[1], bh[2], bh[3], sb + EOFF_BHI + off);
                LDSM4(bl[0], bl[1], bl[2], bl[3], sb + EOFF_BLO + off);
                #pragma unroll
                for (int half = 0; half < 2; half++) {
                    int nc = 2 * jj + half;
                    uint32_t b0h = bh[2 * half], b1h = bh[2 * half + 1];
                    uint32_t b0l = bl[2 * half], b1l = bl[2 * half + 1];
                    #pragma unroll
                    for (int ms = 0; ms < 2; ms++) {
                        mma_bf16(d[ms][nc], ah[ms][0], ah[ms][1], ah[ms][2],
                                 ah[ms][3], b0h, b1h);
                        mma_bf16(d[ms][nc], ah[ms][0], ah[ms][1], ah[ms][2],
                                 ah[ms][3], b0l, b1l);
                        mma_bf16(d[ms][nc], al[ms][0], al[ms][1], al[ms][2],
                                 al[ms][3], b0h, b1h);
                    }
                }
            }
        }
        __syncwarp();  // A reads done; A smem now reusable as K/Q buffers

        // ---- epilogue: two 16-row rounds with coalesced K/Q smem gather ----
        #pragma unroll
        for (int ms = 0; ms < 2; ms++) {
            {   // gather K[s], Q[d] rows: 2 rows per LDG.128 request
                int rowpair = lane >> 4, c = lane & 15;
                #pragma unroll
                for (int pp = 0; pp < 8; pp++) {
                    int rl = 2 * pp + rowpair;
                    int rb = 32 * w + 16 * ms + rl;
                    long long s = si[rb], dd = di[rb];
                    float4 kv = *(const float4*)&g_K[s * HID + c * 4];
                    float4 qv = *(const float4*)&g_Q[dd * HID + c * 4];
                    int off = kq_off(rl, 2 * c);
                    *(float4*)(Ksm + off) = kv;
                    *(float4*)(Qsm + off) = qv;
                }
            }
            __syncwarp();

            #pragma unroll
            for (int hh = 0; hh < 2; hh++) {
                int rl = g + 8 * hh;
                int rb = 32 * w + 16 * ms + rl;
                long long E = base + rb;
                long long s = si[rb];
                float2* eo = (float2*)&e_out[E * HID];
                float hs[8];
                #pragma unroll
                for (int nc = 0; nc < 8; nc++) {
                    float2 kv = *(const float2*)(Ksm + kq_off(rl, 4 * nc + t));
                    float2 qv = *(const float2*)(Qsm + kq_off(rl, 4 * nc + t));
                    float2 bev = *(const float2*)&bes[8 * nc + 2 * t];
                    float sc0 = fmaf(kv.x * qv.x, INV_SQRT8,
                                     d[ms][nc][2 * hh] + bev.x);
                    float sc1 = fmaf(kv.y * qv.y, INV_SQRT8,
                                     d[ms][nc][2 * hh + 1] + bev.y);
                    eo[4 * nc + t] = make_float2(sc0, sc1);
                    hs[nc] = sc0 + sc1;
                }
                #pragma unroll
                for (int nc = 0; nc < 8; nc++) {
                    hs[nc] += __shfl_xor_sync(0xffffffffu, hs[nc], 1);
                    hs[nc] += __shfl_xor_sync(0xffffffffu, hs[nc], 2);
                }
                float a0 = __expf(fminf(fmaxf(hs[2 * t], -5.0f), 5.0f));
                float a1 = __expf(fminf(fmaxf(hs[2 * t + 1], -5.0f), 5.0f));
                red_add_v2(&g_z[s * 8 + 2 * t], a0, a1);
                if (t == 0) red_add_f32(&g_cnt[s], 1.0f);
            }
            __syncwarp();
        }
    }
}

// ------------- final: h_out[n,h,:] = V[n,h,:]*S_h/(S_h/max(cnt,1)+1e-6) ----
__global__ void final_kernel(float* __restrict__ h_out) {
    int i = blockIdx.x * blockDim.x + threadIdx.x;
    if (i >= N_NODES * HID / 4) return;
    int n = i >> 4;
    int cg = i & 15;
    float S = g_z[n * 8 + (cg >> 1)];
    float cnt = g_cnt[n];
    float f = S / (S / fmaxf(cnt, 1.0f) + 1e-6f);
    float4 v = ((const float4*)g_V)[i];
    v.x *= f; v.y *= f; v.z *= f; v.w *= f;
    ((float4*)h_out)[i] = v;
}

// ---------------------------------------------------------------------------
extern "C" void kernel_launch(void* const* d_in, const int* in_sizes, int n_in,
                              void* d_out, int out_size) {
    const void* ei = d_in[0];
    const float* h = (const float*)d_in[1];
    const float* e = (const float*)d_in[2];
    const float* WQ = (const float*)d_in[3];
    const float* bQ = (const float*)d_in[4];
    const float* WK = (const float*)d_in[5];
    const float* bK = (const float*)d_in[6];
    const float* WV = (const float*)d_in[7];
    const float* bV = (const float*)d_in[8];
    const float* We = (const float*)d_in[9];
    const float* be = (const float*)d_in[10];

    float* out = (float*)d_out;
    float* h_out = out;
    float* e_out = out + (long long)N_NODES * HID;

    static int attr_done = 0;
    const int PROJ_SMEM = (24576 + 16 * 512) * 4;  // 131072 B
    if (!attr_done) {
        cudaFuncSetAttribute(proj_fused_kernel,
                             cudaFuncAttributeMaxDynamicSharedMemorySize,
                             PROJ_SMEM);
        cudaFuncSetAttribute(edge_mma_kernel,
                             cudaFuncAttributeMaxDynamicSharedMemorySize,
                             EDGE_SMEM);
        attr_done = 1;
    }

    dummy_kernel<<<1, 32>>>();   // keeps ncu's captured launch on the edge kernel
    zero_detect_kernel<<<391, 256>>>(ei);
    proj_fused_kernel<<<782, 512, PROJ_SMEM>>>(h, WQ, bQ, WK, bK, WV, bV);
    edge_mma_kernel<<<592, 128, EDGE_SMEM>>>(ei, e, We, be, e_out);
    final_kernel<<<(N_NODES * HID / 4 + 255) / 256, 256>>>(h_out);
}